// round 15
// baseline (speedup 1.0000x reference)
#include <cuda_runtime.h>
#include <cuda_bf16.h>
#include <cuda_fp16.h>
#include <math.h>
#include <stdint.h>

// ---------------- scratch (device globals; no allocation allowed) ----------------
__device__ float g_deltas[32768 * 128];          // [q][m*16 + l*8 + k*2 + comp]
__device__ float g_A[32768 * 64];                // [q][m*8 + s]  (softmaxed)
__device__ __half g_wx0h[16 * 64 * 64 * 16];     // [b*8+m][y*64+x][c]  fp16
__device__ __half g_wx1h[16 * 128 * 128 * 16];
__device__ __nv_bfloat16 g_pre_hi[32768 * 128];  // sampled pre, bf16 hi/lo row planes
__device__ __nv_bfloat16 g_pre_lo[32768 * 128];

// weights in MMA-FRAGMENT order: frag[nblk][ks][lane][2] uint32 (bf16x2 pairs)
__device__ __nv_bfloat16 g_Wq_hi[16384],  g_Wq_lo[16384];
__device__ __nv_bfloat16 g_Wda_hi[24576], g_Wda_lo[24576];   // Wd (n<128) ++ Wa
__device__ __nv_bfloat16 g_Wp_hi[16384],  g_Wp_lo[16384];
__device__ __nv_bfloat16 g_Wm_hi[16384],  g_Wm_lo[16384];

constexpr int LO_A = 64 * 272;   // lo-plane byte offset for 64-row tiles (mega)
constexpr int LO_F = 32 * 272;   // lo-plane byte offset for 32-row tiles (final)

// ---------------- helpers ----------------
__device__ __forceinline__ uint32_t smem_u32(const void* p) {
    uint32_t a;
    asm("{ .reg .u64 t; cvta.to.shared.u64 t, %1; cvt.u32.u64 %0, t; }" : "=r"(a) : "l"(p));
    return a;
}
__device__ __forceinline__ void ldm_x4(uint32_t* r, uint32_t addr) {
    asm volatile("ldmatrix.sync.aligned.m8n8.x4.shared.b16 {%0,%1,%2,%3}, [%4];"
        : "=r"(r[0]), "=r"(r[1]), "=r"(r[2]), "=r"(r[3]) : "r"(addr));
}
__device__ __forceinline__ void mma_bf16(float* d, const uint32_t* a, const uint32_t* b) {
    asm volatile("mma.sync.aligned.m16n8k16.row.col.f32.bf16.bf16.f32 "
        "{%0,%1,%2,%3}, {%4,%5,%6,%7}, {%8,%9}, {%0,%1,%2,%3};"
        : "+f"(d[0]), "+f"(d[1]), "+f"(d[2]), "+f"(d[3])
        : "r"(a[0]), "r"(a[1]), "r"(a[2]), "r"(a[3]), "r"(b[0]), "r"(b[1]));
}
__device__ __forceinline__ void cp16(uint32_t dst, const void* src) {
    asm volatile("cp.async.cg.shared.global [%0], [%1], 16;" :: "r"(dst), "l"(src) : "memory");
}
__device__ __forceinline__ void cvt2(float f0, float f1, uint32_t& hi, uint32_t& lo) {
    __nv_bfloat162 h2 = __floats2bfloat162_rn(f0, f1);
    float2 hb = __bfloat1622float2(h2);
    __nv_bfloat162 l2 = __floats2bfloat162_rn(f0 - hb.x, f1 - hb.y);
    hi = *reinterpret_cast<uint32_t*>(&h2);
    lo = *reinterpret_cast<uint32_t*>(&l2);
}

// load 64x128 fp32 tile -> hi/lo bf16 planes in smem (272B padded rows)
__device__ __forceinline__ void load_tile_fp32(const float* __restrict__ X,
                                               char* smem, int tid) {
    float4 v[8];
    #pragma unroll
    for (int it = 0; it < 8; it++) {
        const int idx = it * 256 + tid;
        v[it] = *(const float4*)(X + (idx >> 5) * 128 + ((idx & 31) << 2));
    }
    #pragma unroll
    for (int it = 0; it < 8; it++) {
        const int idx = it * 256 + tid;
        const int r = idx >> 5, c4 = (idx & 31) << 2;
        uint32_t h0, l0, h1, l1;
        cvt2(v[it].x, v[it].y, h0, l0);
        cvt2(v[it].z, v[it].w, h1, l1);
        *(uint2*)(smem + r * 272 + c4 * 2) = make_uint2(h0, h1);
        *(uint2*)(smem + LO_A + r * 272 + c4 * 2) = make_uint2(l0, l1);
    }
}

// 3-term MMA mainloop: A from smem planes (ldmatrix), B frags coalesced from global.
template <int NT, int MI, int LOFF>
__device__ __forceinline__ void mma_loop(uint32_t aB,
    const __nv_bfloat16* __restrict__ Bh, const __nv_bfloat16* __restrict__ Bl,
    int fragBase, float (*acc)[4])
{
    #pragma unroll
    for (int ks = 0; ks < 8; ks++) {
        uint32_t ah[MI][4], al[MI][4];
        #pragma unroll
        for (int mi = 0; mi < MI; mi++) {
            ldm_x4(ah[mi], aB + mi * 16 * 272 + ks * 32);
            ldm_x4(al[mi], aB + LOFF + mi * 16 * 272 + ks * 32);
        }
        uint32_t bh[NT][2], bl[NT][2];
        #pragma unroll
        for (int j = 0; j < NT; j++) {
            const int o = fragBase + j * 1024 + ks * 128;
            const uint2 vh = *(const uint2*)(Bh + o);
            const uint2 vl = *(const uint2*)(Bl + o);
            bh[j][0] = vh.x; bh[j][1] = vh.y;
            bl[j][0] = vl.x; bl[j][1] = vl.y;
        }
        #pragma unroll
        for (int mi = 0; mi < MI; mi++)
            #pragma unroll
            for (int j = 0; j < NT; j++) {
                mma_bf16(acc[mi * NT + j], ah[mi], bh[j]);
                mma_bf16(acc[mi * NT + j], ah[mi], bl[j]);
                mma_bf16(acc[mi * NT + j], al[mi], bh[j]);
            }
    }
}

// =================================================================================
// Weight prep (fragment-coalesced): warp <-> fragment; lane l writes its own uint2.
// 576 fragments: [0,128) Wq, [128,320) Wda, [320,448) Wp, [448,576) Wm.
// =================================================================================
__global__ void __launch_bounds__(256) k_prep(
    const float* __restrict__ Wq, const float* __restrict__ Wd,
    const float* __restrict__ Wa, const float* __restrict__ Wp,
    const float* __restrict__ Wm)
{
    const int t = blockIdx.x * 256 + threadIdx.x;   // 72 blocks = 18432 = 576*32
    const int lane = t & 31;
    const int frag = t >> 5;

    const float* src = nullptr;
    __nv_bfloat16 *dhi, *dlo;
    int fragL;
    bool wda = false;
    if (frag < 128)      { src = Wq; dhi = g_Wq_hi; dlo = g_Wq_lo; fragL = frag; }
    else if (frag < 320) { wda = true; dhi = g_Wda_hi; dlo = g_Wda_lo; fragL = frag - 128; }
    else if (frag < 448) { src = Wp; dhi = g_Wp_hi; dlo = g_Wp_lo; fragL = frag - 320; }
    else                 { src = Wm; dhi = g_Wm_hi; dlo = g_Wm_lo; fragL = frag - 448; }

    const int nblk = fragL >> 3, ks = fragL & 7;
    const int n = nblk * 8 + (lane >> 2);
    const int k0 = ks * 16 + (lane & 3) * 2;

    float wv[4];
    #pragma unroll
    for (int i = 0; i < 4; i++) {
        const int k = k0 + (i >> 1) * 8 + (i & 1);
        wv[i] = wda ? ((n < 128) ? Wd[k * 128 + n] : Wa[k * 64 + (n - 128)])
                    : src[k * 128 + n];
    }
    uint32_t h0, l0, h1, l1;
    cvt2(wv[0], wv[1], h0, l0);
    cvt2(wv[2], wv[3], h1, l1);
    *(uint2*)(dhi + fragL * 128 + lane * 4) = make_uint2(h0, h1);
    *(uint2*)(dlo + fragL * 128 + lane * 4) = make_uint2(l0, l1);
}

// =================================================================================
// MEGA kernel: blocks [0,512) = fused QDA; blocks [512,1152) = Wx projections.
// =================================================================================
__global__ void __launch_bounds__(256, 2) k_mega(
    const float* __restrict__ z_q, const float* __restrict__ x0,
    const float* __restrict__ x1,
    const float* __restrict__ bq, const float* __restrict__ bd,
    const float* __restrict__ ba, const float* __restrict__ bp)
{
    extern __shared__ char smem[];
    float* sBias = (float*)(smem + 2 * LO_A);
    const int tid = threadIdx.x;
    const uint32_t sb = smem_u32(smem);
    const int l = tid & 31, w = tid >> 5;
    const int m0 = (w & 1) * 32;
    const int rl = l >> 2, nc = (l & 3) * 2;
    const uint32_t aB = sb + (uint32_t)(m0 + (l & 15)) * 272 + ((l >> 4) << 4);

    if (blockIdx.x < 512) {
        // ================= QDA path =================
        const int r0 = blockIdx.x * 64;
        load_tile_fp32(z_q + (size_t)r0 * 128, smem, tid);
        if (tid < 128) sBias[tid] = bq[tid];
        else sBias[tid] = bd[tid - 128];
        if (tid < 64) sBias[256 + tid] = ba[tid];
        __syncthreads();

        // ---- GEMM1: zq = z @ Wq  (N=128, NT=4) ----
        {
            const int n0 = (w >> 1) * 32;
            const int fragBase = (n0 >> 3) * 1024 + l * 4;
            float acc[8][4];
            #pragma unroll
            for (int i = 0; i < 8; i++)
                #pragma unroll
                for (int c = 0; c < 4; c++) acc[i][c] = 0.f;
            mma_loop<4, 2, LO_A>(aB, g_Wq_hi, g_Wq_lo, fragBase, acc);
            __syncthreads();

            // epilogue: zq + bq -> SAME smem planes as bf16 hi/lo
            #pragma unroll
            for (int mi = 0; mi < 2; mi++) {
                const int row0 = m0 + mi * 16 + rl;
                #pragma unroll
                for (int j = 0; j < 4; j++) {
                    const int n = n0 + j * 8 + nc;
                    const float b0 = sBias[n], b1 = sBias[n + 1];
                    uint32_t h, lo;
                    cvt2(acc[mi * 4 + j][0] + b0, acc[mi * 4 + j][1] + b1, h, lo);
                    *(uint32_t*)(smem + row0 * 272 + n * 2) = h;
                    *(uint32_t*)(smem + LO_A + row0 * 272 + n * 2) = lo;
                    cvt2(acc[mi * 4 + j][2] + b0, acc[mi * 4 + j][3] + b1, h, lo);
                    *(uint32_t*)(smem + (row0 + 8) * 272 + n * 2) = h;
                    *(uint32_t*)(smem + LO_A + (row0 + 8) * 272 + n * 2) = lo;
                }
            }
        }
        __syncthreads();

        // ---- GEMM2: [deltas | A] = zq @ Wda  (N=192, NT=6) ----
        {
            const int n0 = (w >> 1) * 48;
            const int fragBase = (n0 >> 3) * 1024 + l * 4;
            float acc[12][4];
            #pragma unroll
            for (int i = 0; i < 12; i++)
                #pragma unroll
                for (int c = 0; c < 4; c++) acc[i][c] = 0.f;
            mma_loop<6, 2, LO_A>(aB, g_Wda_hi, g_Wda_lo, fragBase, acc);

            #pragma unroll
            for (int mi = 0; mi < 2; mi++) {
                const int grow0 = r0 + m0 + mi * 16 + rl;
                const int grow1 = grow0 + 8;
                #pragma unroll
                for (int j = 0; j < 6; j++) {
                    const int n = n0 + j * 8 + nc;
                    const float b0 = sBias[128 + n], b1 = sBias[128 + n + 1];
                    const float v00 = acc[mi * 6 + j][0] + b0, v01 = acc[mi * 6 + j][1] + b1;
                    const float v10 = acc[mi * 6 + j][2] + b0, v11 = acc[mi * 6 + j][3] + b1;
                    if (n < 128) {
                        *(float2*)(g_deltas + (size_t)grow0 * 128 + n) = make_float2(v00, v01);
                        *(float2*)(g_deltas + (size_t)grow1 * 128 + n) = make_float2(v10, v11);
                    } else {
                        float mx = fmaxf(v00, v01);
                        mx = fmaxf(mx, __shfl_xor_sync(0xffffffffu, mx, 1));
                        mx = fmaxf(mx, __shfl_xor_sync(0xffffffffu, mx, 2));
                        float e0 = expf(v00 - mx), e1 = expf(v01 - mx);
                        float s = e0 + e1;
                        s += __shfl_xor_sync(0xffffffffu, s, 1);
                        s += __shfl_xor_sync(0xffffffffu, s, 2);
                        const float inv = 1.f / s;
                        *(float2*)(g_A + (size_t)grow0 * 64 + (n - 128))
                            = make_float2(e0 * inv, e1 * inv);

                        float mx2 = fmaxf(v10, v11);
                        mx2 = fmaxf(mx2, __shfl_xor_sync(0xffffffffu, mx2, 1));
                        mx2 = fmaxf(mx2, __shfl_xor_sync(0xffffffffu, mx2, 2));
                        float f0 = expf(v10 - mx2), f1 = expf(v11 - mx2);
                        float s2 = f0 + f1;
                        s2 += __shfl_xor_sync(0xffffffffu, s2, 1);
                        s2 += __shfl_xor_sync(0xffffffffu, s2, 2);
                        const float inv2 = 1.f / s2;
                        *(float2*)(g_A + (size_t)grow1 * 64 + (n - 128))
                            = make_float2(f0 * inv2, f1 * inv2);
                    }
                }
            }
        }
    } else {
        // ================= projection path =================
        const int bid = blockIdx.x - 512;
        const float* Xsrc;
        __half* o16;
        int hwshift, r0;
        if (bid < 128) { Xsrc = x0; o16 = g_wx0h; hwshift = 12; r0 = bid * 64; }
        else { Xsrc = x1; o16 = g_wx1h; hwshift = 14; r0 = (bid - 128) * 64; }

        load_tile_fp32(Xsrc + (size_t)r0 * 128, smem, tid);
        if (tid < 128) sBias[tid] = bp[tid];
        __syncthreads();

        const int n0 = (w >> 1) * 32;
        const int fragBase = (n0 >> 3) * 1024 + l * 4;
        float acc[8][4];
        #pragma unroll
        for (int i = 0; i < 8; i++)
            #pragma unroll
            for (int c = 0; c < 4; c++) acc[i][c] = 0.f;
        mma_loop<4, 2, LO_A>(aB, g_Wp_hi, g_Wp_lo, fragBase, acc);

        const int msk = (1 << hwshift) - 1;
        #pragma unroll
        for (int mi = 0; mi < 2; mi++) {
            const int grow0 = r0 + m0 + mi * 16 + rl;
            const int grow1 = grow0 + 8;
            #pragma unroll
            for (int j = 0; j < 4; j++) {
                const int n = n0 + j * 8 + nc;
                const float b0 = sBias[n], b1 = sBias[n + 1];
                const int mh = n >> 4, c = n & 15;
                __half* o0 = o16 + ((((size_t)((grow0 >> hwshift) * 8 + mh)) << hwshift)
                                   + (grow0 & msk)) * 16 + c;
                __half* o1 = o16 + ((((size_t)((grow1 >> hwshift) * 8 + mh)) << hwshift)
                                   + (grow1 & msk)) * 16 + c;
                *(__half2*)o0 = __floats2half2_rn(acc[mi*4+j][0] + b0, acc[mi*4+j][1] + b1);
                *(__half2*)o1 = __floats2half2_rn(acc[mi*4+j][2] + b0, acc[mi*4+j][3] + b1);
            }
        }
    }
}

// =================================================================================
// Sampler: thread = (n, qp, lane), loops all 4 hb.  A weights loaded ONCE per
// thread (was 4x), index decode shared, per-thread MLP ~16 loads, output is one
// contiguous 32B row segment per plane.  2048 blocks of 256.
// =================================================================================
__global__ void __launch_bounds__(256) k_sample(const float* __restrict__ p_q)
{
    const int t    = blockIdx.x * 256 + threadIdx.x;   // 524288 threads
    const int lane = t & 1;                            // channel half
    const int g    = t >> 1;
    const int qp   = g & 16383;
    const int n    = g >> 14;
    const int b = n >> 3, m = n & 7;
    const int ks = qp >> 12;
    const int ws = (qp >> 5) & 127;
    const int hs0 = (qp & 31) << 2;

    // attention weights: one load, shared across all 4 hb
    const float4* ap = (const float4*)(g_A + (b * 16384 + qp) * 64 + m * 8);
    const float4 A0 = ap[0], A1 = ap[1];

    float res[4][2];
    #pragma unroll
    for (int hb = 0; hb < 4; hb++) {
        const int hs = hs0 + hb;
        const float* dptr = g_deltas + (b * 16384 + hs * 128 + ws) * 128 + m * 16 + ks * 2;
        const float2 d0 = *(const float2*)dptr;
        const float2 d1 = *(const float2*)(dptr + 8);
        const float2 pq = *(const float2*)(p_q + ((m & 1) * 16384 + hs * 128 + ws) * 2);

        #pragma unroll
        for (int l = 0; l < 2; l++) {
            const int wl = l ? 128 : 64;
            const float sc = l ? 127.f : 63.f;
            const float mult = (float)wl / sc;
            const __half* img = (l ? g_wx1h : g_wx0h) + n * (wl * wl * 16) + lane * 8;
            const float2 dxy = l ? d1 : d0;

            const float ix = fmaf(fmaf(pq.x, sc, dxy.x), mult, -0.5f);
            const float iy = fmaf(fmaf(pq.y, sc, dxy.y), mult, -0.5f);
            const float xf = floorf(ix), yf = floorf(iy);
            const float fx1 = ix - xf, fy1 = iy - yf;
            const float fx0 = 1.f - fx1, fy0 = 1.f - fy1;
            const int x0 = (int)xf, y0 = (int)yf;

            float a0 = 0.f, a1 = 0.f, a2 = 0.f, a3 = 0.f;
            float a4 = 0.f, a5 = 0.f, a6 = 0.f, a7 = 0.f;
            #pragma unroll
            for (int tap = 0; tap < 4; tap++) {
                const int xi = x0 + (tap & 1);
                const int yi = y0 + (tap >> 1);
                const float w = ((tap & 1) ? fx1 : fx0) * ((tap >> 1) ? fy1 : fy0);
                if (xi >= 0 && xi < wl && yi >= 0 && yi < wl) {
                    const uint4 v = *(const uint4*)(img + ((yi * wl + xi) << 4));
                    const __half2* hp = (const __half2*)&v;
                    float2 f0 = __half22float2(hp[0]);
                    float2 f1 = __half22float2(hp[1]);
                    float2 f2 = __half22float2(hp[2]);
                    float2 f3 = __half22float2(hp[3]);
                    a0 = fmaf(w, f0.x, a0); a1 = fmaf(w, f0.y, a1);
                    a2 = fmaf(w, f1.x, a2); a3 = fmaf(w, f1.y, a3);
                    a4 = fmaf(w, f2.x, a4); a5 = fmaf(w, f2.y, a5);
                    a6 = fmaf(w, f3.x, a6); a7 = fmaf(w, f3.y, a7);
                }
            }
            res[hb][l] = A0.x * a0 + A0.y * a1 + A0.z * a2 + A0.w * a3
                       + A1.x * a4 + A1.y * a5 + A1.z * a6 + A1.w * a7;
        }
    }

    // exchange channel halves and emit one contiguous 32B segment per plane
    uint32_t hiw[8], low[8];
    #pragma unroll
    for (int hb = 0; hb < 4; hb++) {
        const float p0 = __shfl_xor_sync(0xffffffffu, res[hb][0], 1);
        const float p1 = __shfl_xor_sync(0xffffffffu, res[hb][1], 1);
        cvt2(res[hb][0], p0, hiw[hb * 2],     low[hb * 2]);
        cvt2(res[hb][1], p1, hiw[hb * 2 + 1], low[hb * 2 + 1]);
    }
    if (lane == 0) {
        const size_t off = (size_t)(b * 16384 + qp) * 128 + m * 16;   // bf16 elems
        uint4* dh = (uint4*)(g_pre_hi + off);
        uint4* dl = (uint4*)(g_pre_lo + off);
        dh[0] = make_uint4(hiw[0], hiw[1], hiw[2], hiw[3]);
        dh[1] = make_uint4(hiw[4], hiw[5], hiw[6], hiw[7]);
        dl[0] = make_uint4(low[0], low[1], low[2], low[3]);
        dl[1] = make_uint4(low[4], low[5], low[6], low[7]);
    }
}

// =================================================================================
// Final GEMM (round-12 proven): out = pre @ Wm + bm.  32-row tiles, cp.async
// ingest of bf16 planes, 1024 blocks, 3 CTAs/SM.
// =================================================================================
__global__ void __launch_bounds__(256, 3) k_final(
    const float* __restrict__ bm, float* __restrict__ out)
{
    extern __shared__ char smem[];
    float* sBias = (float*)(smem + 2 * LO_F);
    const int tid = threadIdx.x;
    const uint32_t sb = smem_u32(smem);
    const int r0 = blockIdx.x * 32;

    #pragma unroll
    for (int it = 0; it < 4; it++) {
        const int idx = it * 256 + tid;      // 1024 16B chunks
        const int pl = idx >> 9;             // 0 hi, 1 lo
        const int r = (idx >> 4) & 31;
        const int seg = idx & 15;
        const __nv_bfloat16* src = (pl ? g_pre_lo : g_pre_hi)
                                   + (size_t)(r0 + r) * 128 + seg * 8;
        cp16(sb + pl * LO_F + r * 272 + seg * 16, src);
    }
    asm volatile("cp.async.commit_group;" ::: "memory");
    if (tid < 128) sBias[tid] = bm[tid];
    asm volatile("cp.async.wait_group 0;" ::: "memory");
    __syncthreads();

    const int l = tid & 31, w = tid >> 5;
    const int m0 = (w & 1) * 16;
    const int n0 = (w >> 1) * 32;
    const uint32_t aB = sb + (uint32_t)(m0 + (l & 15)) * 272 + ((l >> 4) << 4);
    const int fragBase = (n0 >> 3) * 1024 + l * 4;

    float acc[4][4];
    #pragma unroll
    for (int i = 0; i < 4; i++)
        #pragma unroll
        for (int c = 0; c < 4; c++) acc[i][c] = 0.f;
    mma_loop<4, 1, LO_F>(aB, g_Wm_hi, g_Wm_lo, fragBase, acc);

    const int rl = l >> 2, nc = (l & 3) * 2;
    const int grow0 = r0 + m0 + rl;
    const int grow1 = grow0 + 8;
    #pragma unroll
    for (int j = 0; j < 4; j++) {
        const int n = n0 + j * 8 + nc;
        const float b0 = sBias[n], b1 = sBias[n + 1];
        *(float2*)(out + (size_t)grow0 * 128 + n)
            = make_float2(acc[j][0] + b0, acc[j][1] + b1);
        *(float2*)(out + (size_t)grow1 * 128 + n)
            = make_float2(acc[j][2] + b0, acc[j][3] + b1);
    }
}

// =================================================================================
extern "C" void kernel_launch(void* const* d_in, const int* in_sizes, int n_in,
                              void* d_out, int out_size)
{
    const float* z_q = (const float*)d_in[0];
    const float* x0  = (const float*)d_in[1];
    const float* x1  = (const float*)d_in[2];
    const float* p_q = (const float*)d_in[3];
    const float* Wq  = (const float*)d_in[4];
    const float* bq  = (const float*)d_in[5];
    const float* Wd  = (const float*)d_in[6];
    const float* bd  = (const float*)d_in[7];
    const float* Wa  = (const float*)d_in[8];
    const float* ba  = (const float*)d_in[9];
    const float* Wp  = (const float*)d_in[10];
    const float* bp  = (const float*)d_in[11];
    const float* Wm  = (const float*)d_in[12];
    const float* bm  = (const float*)d_in[13];
    float* out = (float*)d_out;

    const int MEGA_SMEM  = 2 * LO_A + 320 * 4;   // 36096
    const int FINAL_SMEM = 2 * LO_F + 128 * 4;   // 17920

    k_prep<<<72, 256>>>(Wq, Wd, Wa, Wp, Wm);
    // fused QDA (blocks 0..511)  +  projections (blocks 512..1151)
    k_mega<<<1152, 256, MEGA_SMEM>>>(z_q, x0, x1, bq, bd, ba, bp);
    // sampling + attention dot (hb-looped, A loaded once) -> bf16 hi/lo row planes
    k_sample<<<2048, 256>>>(p_q);
    // out = pre @ Wm + bm  (32-row tiles, cp.async ingest)
    k_final<<<1024, 256, FINAL_SMEM>>>(bm, out);
}

// round 16
// speedup vs baseline: 1.1156x; 1.1156x over previous
#include <cuda_runtime.h>
#include <cuda_bf16.h>
#include <cuda_fp16.h>
#include <math.h>
#include <stdint.h>

// ---------------- scratch (device globals; no allocation allowed) ----------------
__device__ float g_deltas[32768 * 128];          // [q][m*16 + l*8 + k*2 + comp]
__device__ float g_A[32768 * 64];                // [q][m*8 + s]  (softmaxed)
__device__ __half g_wx0h[16 * 64 * 64 * 16];     // [b*8+m][y*64+x][c]  fp16
__device__ __half g_wx1h[16 * 128 * 128 * 16];
__device__ __nv_bfloat16 g_pre_hi[32768 * 128];  // sampled pre, bf16 hi/lo row planes
__device__ __nv_bfloat16 g_pre_lo[32768 * 128];

// weights in MMA-FRAGMENT order: frag[nblk][ks][lane][2] pairs
__device__ __nv_bfloat16 g_Wq_hi[16384];                     // bf16 hi only (2-term QDA)
__device__ __nv_bfloat16 g_Wda_hi[24576];                    // Wd (n<128) ++ Wa, hi only
__device__ __half        g_Wp_h16[16384];                    // fp16 single plane (proj)
__device__ __nv_bfloat16 g_Wm_hi[16384], g_Wm_lo[16384];     // 3-term (final)

constexpr int LO_A = 64 * 272;   // lo-plane byte offset for 64-row tiles (mega)
constexpr int LO_F = 32 * 272;   // lo-plane byte offset for 32-row tiles (final)

// ---------------- helpers ----------------
__device__ __forceinline__ uint32_t smem_u32(const void* p) {
    uint32_t a;
    asm("{ .reg .u64 t; cvta.to.shared.u64 t, %1; cvt.u32.u64 %0, t; }" : "=r"(a) : "l"(p));
    return a;
}
__device__ __forceinline__ void ldm_x4(uint32_t* r, uint32_t addr) {
    asm volatile("ldmatrix.sync.aligned.m8n8.x4.shared.b16 {%0,%1,%2,%3}, [%4];"
        : "=r"(r[0]), "=r"(r[1]), "=r"(r[2]), "=r"(r[3]) : "r"(addr));
}
__device__ __forceinline__ void mma_bf16(float* d, const uint32_t* a, const uint32_t* b) {
    asm volatile("mma.sync.aligned.m16n8k16.row.col.f32.bf16.bf16.f32 "
        "{%0,%1,%2,%3}, {%4,%5,%6,%7}, {%8,%9}, {%0,%1,%2,%3};"
        : "+f"(d[0]), "+f"(d[1]), "+f"(d[2]), "+f"(d[3])
        : "r"(a[0]), "r"(a[1]), "r"(a[2]), "r"(a[3]), "r"(b[0]), "r"(b[1]));
}
__device__ __forceinline__ void mma_f16(float* d, const uint32_t* a, const uint32_t* b) {
    asm volatile("mma.sync.aligned.m16n8k16.row.col.f32.f16.f16.f32 "
        "{%0,%1,%2,%3}, {%4,%5,%6,%7}, {%8,%9}, {%0,%1,%2,%3};"
        : "+f"(d[0]), "+f"(d[1]), "+f"(d[2]), "+f"(d[3])
        : "r"(a[0]), "r"(a[1]), "r"(a[2]), "r"(a[3]), "r"(b[0]), "r"(b[1]));
}
__device__ __forceinline__ void cp16(uint32_t dst, const void* src) {
    asm volatile("cp.async.cg.shared.global [%0], [%1], 16;" :: "r"(dst), "l"(src) : "memory");
}
__device__ __forceinline__ void cvt2(float f0, float f1, uint32_t& hi, uint32_t& lo) {
    __nv_bfloat162 h2 = __floats2bfloat162_rn(f0, f1);
    float2 hb = __bfloat1622float2(h2);
    __nv_bfloat162 l2 = __floats2bfloat162_rn(f0 - hb.x, f1 - hb.y);
    hi = *reinterpret_cast<uint32_t*>(&h2);
    lo = *reinterpret_cast<uint32_t*>(&l2);
}

// load 64x128 fp32 tile -> hi/lo bf16 planes in smem (272B padded rows)
__device__ __forceinline__ void load_tile_fp32(const float* __restrict__ X,
                                               char* smem, int tid) {
    float4 v[8];
    #pragma unroll
    for (int it = 0; it < 8; it++) {
        const int idx = it * 256 + tid;
        v[it] = *(const float4*)(X + (idx >> 5) * 128 + ((idx & 31) << 2));
    }
    #pragma unroll
    for (int it = 0; it < 8; it++) {
        const int idx = it * 256 + tid;
        const int r = idx >> 5, c4 = (idx & 31) << 2;
        uint32_t h0, l0, h1, l1;
        cvt2(v[it].x, v[it].y, h0, l0);
        cvt2(v[it].z, v[it].w, h1, l1);
        *(uint2*)(smem + r * 272 + c4 * 2) = make_uint2(h0, h1);
        *(uint2*)(smem + LO_A + r * 272 + c4 * 2) = make_uint2(l0, l1);
    }
}

// load 64x128 fp32 tile -> SINGLE fp16 plane in smem (272B padded rows)
__device__ __forceinline__ void load_tile_h16(const float* __restrict__ X,
                                              char* smem, int tid) {
    float4 v[8];
    #pragma unroll
    for (int it = 0; it < 8; it++) {
        const int idx = it * 256 + tid;
        v[it] = *(const float4*)(X + (idx >> 5) * 128 + ((idx & 31) << 2));
    }
    #pragma unroll
    for (int it = 0; it < 8; it++) {
        const int idx = it * 256 + tid;
        const int r = idx >> 5, c4 = (idx & 31) << 2;
        __half2 a = __floats2half2_rn(v[it].x, v[it].y);
        __half2 b = __floats2half2_rn(v[it].z, v[it].w);
        *(uint2*)(smem + r * 272 + c4 * 2)
            = make_uint2(*reinterpret_cast<uint32_t*>(&a), *reinterpret_cast<uint32_t*>(&b));
    }
}

// 3-term bf16 mainloop (final GEMM): A hi/lo planes, B hi/lo fragments.
template <int NT, int MI, int LOFF>
__device__ __forceinline__ void mma_loop3(uint32_t aB,
    const __nv_bfloat16* __restrict__ Bh, const __nv_bfloat16* __restrict__ Bl,
    int fragBase, float (*acc)[4])
{
    #pragma unroll
    for (int ks = 0; ks < 8; ks++) {
        uint32_t ah[MI][4], al[MI][4];
        #pragma unroll
        for (int mi = 0; mi < MI; mi++) {
            ldm_x4(ah[mi], aB + mi * 16 * 272 + ks * 32);
            ldm_x4(al[mi], aB + LOFF + mi * 16 * 272 + ks * 32);
        }
        uint32_t bh[NT][2], bl[NT][2];
        #pragma unroll
        for (int j = 0; j < NT; j++) {
            const int o = fragBase + j * 1024 + ks * 128;
            const uint2 vh = *(const uint2*)(Bh + o);
            const uint2 vl = *(const uint2*)(Bl + o);
            bh[j][0] = vh.x; bh[j][1] = vh.y;
            bl[j][0] = vl.x; bl[j][1] = vl.y;
        }
        #pragma unroll
        for (int mi = 0; mi < MI; mi++)
            #pragma unroll
            for (int j = 0; j < NT; j++) {
                mma_bf16(acc[mi * NT + j], ah[mi], bh[j]);
                mma_bf16(acc[mi * NT + j], ah[mi], bl[j]);
                mma_bf16(acc[mi * NT + j], al[mi], bh[j]);
            }
    }
}

// 2-term bf16 mainloop (QDA): A hi/lo planes, B hi fragments only.
template <int NT, int MI, int LOFF>
__device__ __forceinline__ void mma_loop2(uint32_t aB,
    const __nv_bfloat16* __restrict__ Bh, int fragBase, float (*acc)[4])
{
    #pragma unroll
    for (int ks = 0; ks < 8; ks++) {
        uint32_t ah[MI][4], al[MI][4];
        #pragma unroll
        for (int mi = 0; mi < MI; mi++) {
            ldm_x4(ah[mi], aB + mi * 16 * 272 + ks * 32);
            ldm_x4(al[mi], aB + LOFF + mi * 16 * 272 + ks * 32);
        }
        uint32_t bh[NT][2];
        #pragma unroll
        for (int j = 0; j < NT; j++) {
            const int o = fragBase + j * 1024 + ks * 128;
            const uint2 vh = *(const uint2*)(Bh + o);
            bh[j][0] = vh.x; bh[j][1] = vh.y;
        }
        #pragma unroll
        for (int mi = 0; mi < MI; mi++)
            #pragma unroll
            for (int j = 0; j < NT; j++) {
                mma_bf16(acc[mi * NT + j], ah[mi], bh[j]);
                mma_bf16(acc[mi * NT + j], al[mi], bh[j]);
            }
    }
}

// single-term fp16 mainloop (projections): A single fp16 plane, B fp16 fragments.
template <int NT, int MI>
__device__ __forceinline__ void mma_loop_h(uint32_t aB,
    const __half* __restrict__ Bh, int fragBase, float (*acc)[4])
{
    #pragma unroll
    for (int ks = 0; ks < 8; ks++) {
        uint32_t ah[MI][4];
        #pragma unroll
        for (int mi = 0; mi < MI; mi++)
            ldm_x4(ah[mi], aB + mi * 16 * 272 + ks * 32);
        uint32_t bh[NT][2];
        #pragma unroll
        for (int j = 0; j < NT; j++) {
            const int o = fragBase + j * 1024 + ks * 128;
            const uint2 vh = *(const uint2*)(Bh + o);
            bh[j][0] = vh.x; bh[j][1] = vh.y;
        }
        #pragma unroll
        for (int mi = 0; mi < MI; mi++)
            #pragma unroll
            for (int j = 0; j < NT; j++)
                mma_f16(acc[mi * NT + j], ah[mi], bh[j]);
    }
}

// =================================================================================
// Weight prep (fragment-coalesced): warp <-> fragment; lane l writes its own pairs.
// 576 fragments: [0,128) Wq(bf16 hi), [128,320) Wda(bf16 hi), [320,448) Wp(fp16),
// [448,576) Wm(bf16 hi+lo).
// =================================================================================
__global__ void __launch_bounds__(256) k_prep(
    const float* __restrict__ Wq, const float* __restrict__ Wd,
    const float* __restrict__ Wa, const float* __restrict__ Wp,
    const float* __restrict__ Wm)
{
    const int t = blockIdx.x * 256 + threadIdx.x;   // 72 blocks = 18432 = 576*32
    const int lane = t & 31;
    const int frag = t >> 5;

    int kind, fragL;
    if (frag < 128)      { kind = 0; fragL = frag; }
    else if (frag < 320) { kind = 1; fragL = frag - 128; }
    else if (frag < 448) { kind = 2; fragL = frag - 320; }
    else                 { kind = 3; fragL = frag - 448; }

    const int nblk = fragL >> 3, ks = fragL & 7;
    const int n = nblk * 8 + (lane >> 2);
    const int k0 = ks * 16 + (lane & 3) * 2;

    float wv[4];
    #pragma unroll
    for (int i = 0; i < 4; i++) {
        const int k = k0 + (i >> 1) * 8 + (i & 1);
        wv[i] = (kind == 0) ? Wq[k * 128 + n]
              : (kind == 1) ? ((n < 128) ? Wd[k * 128 + n] : Wa[k * 64 + (n - 128)])
              : (kind == 2) ? Wp[k * 128 + n]
                            : Wm[k * 128 + n];
    }
    const int e = fragL * 128 + lane * 4;
    if (kind == 2) {
        __half2 a = __floats2half2_rn(wv[0], wv[1]);
        __half2 b = __floats2half2_rn(wv[2], wv[3]);
        *(uint2*)(g_Wp_h16 + e)
            = make_uint2(*reinterpret_cast<uint32_t*>(&a), *reinterpret_cast<uint32_t*>(&b));
    } else {
        uint32_t h0, l0, h1, l1;
        cvt2(wv[0], wv[1], h0, l0);
        cvt2(wv[2], wv[3], h1, l1);
        __nv_bfloat16* dhi = (kind == 0) ? g_Wq_hi : (kind == 1) ? g_Wda_hi : g_Wm_hi;
        *(uint2*)(dhi + e) = make_uint2(h0, h1);
        if (kind == 3) *(uint2*)(g_Wm_lo + e) = make_uint2(l0, l1);
    }
}

// =================================================================================
// MEGA kernel: blocks [0,512) = fused QDA (2-term); [512,1152) = projections (fp16).
// =================================================================================
__global__ void __launch_bounds__(256, 2) k_mega(
    const float* __restrict__ z_q, const float* __restrict__ x0,
    const float* __restrict__ x1,
    const float* __restrict__ bq, const float* __restrict__ bd,
    const float* __restrict__ ba, const float* __restrict__ bp)
{
    extern __shared__ char smem[];
    float* sBias = (float*)(smem + 2 * LO_A);
    const int tid = threadIdx.x;
    const uint32_t sb = smem_u32(smem);
    const int l = tid & 31, w = tid >> 5;
    const int m0 = (w & 1) * 32;
    const int rl = l >> 2, nc = (l & 3) * 2;
    const uint32_t aB = sb + (uint32_t)(m0 + (l & 15)) * 272 + ((l >> 4) << 4);

    if (blockIdx.x < 512) {
        // ================= QDA path (2-term bf16) =================
        const int r0 = blockIdx.x * 64;
        load_tile_fp32(z_q + (size_t)r0 * 128, smem, tid);
        if (tid < 128) sBias[tid] = bq[tid];
        else sBias[tid] = bd[tid - 128];
        if (tid < 64) sBias[256 + tid] = ba[tid];
        __syncthreads();

        // ---- GEMM1: zq = z @ Wq  (N=128, NT=4) ----
        {
            const int n0 = (w >> 1) * 32;
            const int fragBase = (n0 >> 3) * 1024 + l * 4;
            float acc[8][4];
            #pragma unroll
            for (int i = 0; i < 8; i++)
                #pragma unroll
                for (int c = 0; c < 4; c++) acc[i][c] = 0.f;
            mma_loop2<4, 2, LO_A>(aB, g_Wq_hi, fragBase, acc);
            __syncthreads();

            // epilogue: zq + bq -> SAME smem planes as bf16 hi/lo
            #pragma unroll
            for (int mi = 0; mi < 2; mi++) {
                const int row0 = m0 + mi * 16 + rl;
                #pragma unroll
                for (int j = 0; j < 4; j++) {
                    const int n = n0 + j * 8 + nc;
                    const float b0 = sBias[n], b1 = sBias[n + 1];
                    uint32_t h, lo;
                    cvt2(acc[mi * 4 + j][0] + b0, acc[mi * 4 + j][1] + b1, h, lo);
                    *(uint32_t*)(smem + row0 * 272 + n * 2) = h;
                    *(uint32_t*)(smem + LO_A + row0 * 272 + n * 2) = lo;
                    cvt2(acc[mi * 4 + j][2] + b0, acc[mi * 4 + j][3] + b1, h, lo);
                    *(uint32_t*)(smem + (row0 + 8) * 272 + n * 2) = h;
                    *(uint32_t*)(smem + LO_A + (row0 + 8) * 272 + n * 2) = lo;
                }
            }
        }
        __syncthreads();

        // ---- GEMM2: [deltas | A] = zq @ Wda  (N=192, NT=6) ----
        {
            const int n0 = (w >> 1) * 48;
            const int fragBase = (n0 >> 3) * 1024 + l * 4;
            float acc[12][4];
            #pragma unroll
            for (int i = 0; i < 12; i++)
                #pragma unroll
                for (int c = 0; c < 4; c++) acc[i][c] = 0.f;
            mma_loop2<6, 2, LO_A>(aB, g_Wda_hi, fragBase, acc);

            #pragma unroll
            for (int mi = 0; mi < 2; mi++) {
                const int grow0 = r0 + m0 + mi * 16 + rl;
                const int grow1 = grow0 + 8;
                #pragma unroll
                for (int j = 0; j < 6; j++) {
                    const int n = n0 + j * 8 + nc;
                    const float b0 = sBias[128 + n], b1 = sBias[128 + n + 1];
                    const float v00 = acc[mi * 6 + j][0] + b0, v01 = acc[mi * 6 + j][1] + b1;
                    const float v10 = acc[mi * 6 + j][2] + b0, v11 = acc[mi * 6 + j][3] + b1;
                    if (n < 128) {
                        *(float2*)(g_deltas + (size_t)grow0 * 128 + n) = make_float2(v00, v01);
                        *(float2*)(g_deltas + (size_t)grow1 * 128 + n) = make_float2(v10, v11);
                    } else {
                        float mx = fmaxf(v00, v01);
                        mx = fmaxf(mx, __shfl_xor_sync(0xffffffffu, mx, 1));
                        mx = fmaxf(mx, __shfl_xor_sync(0xffffffffu, mx, 2));
                        float e0 = expf(v00 - mx), e1 = expf(v01 - mx);
                        float s = e0 + e1;
                        s += __shfl_xor_sync(0xffffffffu, s, 1);
                        s += __shfl_xor_sync(0xffffffffu, s, 2);
                        const float inv = 1.f / s;
                        *(float2*)(g_A + (size_t)grow0 * 64 + (n - 128))
                            = make_float2(e0 * inv, e1 * inv);

                        float mx2 = fmaxf(v10, v11);
                        mx2 = fmaxf(mx2, __shfl_xor_sync(0xffffffffu, mx2, 1));
                        mx2 = fmaxf(mx2, __shfl_xor_sync(0xffffffffu, mx2, 2));
                        float f0 = expf(v10 - mx2), f1 = expf(v11 - mx2);
                        float s2 = f0 + f1;
                        s2 += __shfl_xor_sync(0xffffffffu, s2, 1);
                        s2 += __shfl_xor_sync(0xffffffffu, s2, 2);
                        const float inv2 = 1.f / s2;
                        *(float2*)(g_A + (size_t)grow1 * 64 + (n - 128))
                            = make_float2(f0 * inv2, f1 * inv2);
                    }
                }
            }
        }
    } else {
        // ================= projection path (single fp16 MMA) =================
        const int bid = blockIdx.x - 512;
        const float* Xsrc;
        __half* o16;
        int hwshift, r0;
        if (bid < 128) { Xsrc = x0; o16 = g_wx0h; hwshift = 12; r0 = bid * 64; }
        else { Xsrc = x1; o16 = g_wx1h; hwshift = 14; r0 = (bid - 128) * 64; }

        load_tile_h16(Xsrc + (size_t)r0 * 128, smem, tid);
        if (tid < 128) sBias[tid] = bp[tid];
        __syncthreads();

        const int n0 = (w >> 1) * 32;
        const int fragBase = (n0 >> 3) * 1024 + l * 4;
        float acc[8][4];
        #pragma unroll
        for (int i = 0; i < 8; i++)
            #pragma unroll
            for (int c = 0; c < 4; c++) acc[i][c] = 0.f;
        mma_loop_h<4, 2>(aB, g_Wp_h16, fragBase, acc);

        const int msk = (1 << hwshift) - 1;
        #pragma unroll
        for (int mi = 0; mi < 2; mi++) {
            const int grow0 = r0 + m0 + mi * 16 + rl;
            const int grow1 = grow0 + 8;
            #pragma unroll
            for (int j = 0; j < 4; j++) {
                const int n = n0 + j * 8 + nc;
                const float b0 = sBias[n], b1 = sBias[n + 1];
                const int mh = n >> 4, c = n & 15;
                __half* o0 = o16 + ((((size_t)((grow0 >> hwshift) * 8 + mh)) << hwshift)
                                   + (grow0 & msk)) * 16 + c;
                __half* o1 = o16 + ((((size_t)((grow1 >> hwshift) * 8 + mh)) << hwshift)
                                   + (grow1 & msk)) * 16 + c;
                *(__half2*)o0 = __floats2half2_rn(acc[mi*4+j][0] + b0, acc[mi*4+j][1] + b1);
                *(__half2*)o1 = __floats2half2_rn(acc[mi*4+j][2] + b0, acc[mi*4+j][3] + b1);
            }
        }
    }
}

// =================================================================================
// Sampler (round-12 proven): 2 lanes per location, fp16 images, both levels per
// thread; writes pre as bf16 hi/lo row planes.  8192 blocks of 256.
// =================================================================================
__global__ void __launch_bounds__(256) k_sample(const float* __restrict__ p_q)
{
    const int t    = blockIdx.x * 256 + threadIdx.x;
    const int lane = t & 1;
    const int loc  = t >> 1;
    const int hb = loc & 3;
    const int qp = (loc >> 2) & 16383;
    const int n  = loc >> 16;
    const int b = n >> 3, m = n & 7;
    const int ks = qp >> 12;
    const int ws = (qp >> 5) & 127;
    const int hs = ((qp & 31) << 2) + hb;

    const float4* ap = (const float4*)(g_A + (b * 16384 + qp) * 64 + m * 8);
    const float4 A0 = ap[0], A1 = ap[1];

    const float* dptr = g_deltas + (b * 16384 + hs * 128 + ws) * 128 + m * 16 + ks * 2;
    const float2 d0 = *(const float2*)dptr;
    const float2 d1 = *(const float2*)(dptr + 8);
    const float2 pq = *(const float2*)(p_q + ((m & 1) * 16384 + hs * 128 + ws) * 2);

    float res[2];
    #pragma unroll
    for (int l = 0; l < 2; l++) {
        const int wl = l ? 128 : 64;
        const float sc = l ? 127.f : 63.f;
        const float mult = (float)wl / sc;
        const __half* img = (l ? g_wx1h : g_wx0h) + n * (wl * wl * 16) + lane * 8;
        const float2 dxy = l ? d1 : d0;

        const float ix = fmaf(fmaf(pq.x, sc, dxy.x), mult, -0.5f);
        const float iy = fmaf(fmaf(pq.y, sc, dxy.y), mult, -0.5f);
        const float xf = floorf(ix), yf = floorf(iy);
        const float fx1 = ix - xf, fy1 = iy - yf;
        const float fx0 = 1.f - fx1, fy0 = 1.f - fy1;
        const int x0 = (int)xf, y0 = (int)yf;

        float a0 = 0.f, a1 = 0.f, a2 = 0.f, a3 = 0.f;
        float a4 = 0.f, a5 = 0.f, a6 = 0.f, a7 = 0.f;
        #pragma unroll
        for (int tap = 0; tap < 4; tap++) {
            const int xi = x0 + (tap & 1);
            const int yi = y0 + (tap >> 1);
            const float w = ((tap & 1) ? fx1 : fx0) * ((tap >> 1) ? fy1 : fy0);
            if (xi >= 0 && xi < wl && yi >= 0 && yi < wl) {
                const uint4 v = *(const uint4*)(img + ((yi * wl + xi) << 4));
                const __half2* hp = (const __half2*)&v;
                float2 f0 = __half22float2(hp[0]);
                float2 f1 = __half22float2(hp[1]);
                float2 f2 = __half22float2(hp[2]);
                float2 f3 = __half22float2(hp[3]);
                a0 = fmaf(w, f0.x, a0); a1 = fmaf(w, f0.y, a1);
                a2 = fmaf(w, f1.x, a2); a3 = fmaf(w, f1.y, a3);
                a4 = fmaf(w, f2.x, a4); a5 = fmaf(w, f2.y, a5);
                a6 = fmaf(w, f3.x, a6); a7 = fmaf(w, f3.y, a7);
            }
        }
        res[l] = A0.x * a0 + A0.y * a1 + A0.z * a2 + A0.w * a3
               + A1.x * a4 + A1.y * a5 + A1.z * a6 + A1.w * a7;
    }
    const float q0 = __shfl_xor_sync(0xffffffffu, res[0], 1);
    const float q1 = __shfl_xor_sync(0xffffffffu, res[1], 1);
    if (lane == 0) {
        const int row = b * 16384 + qp;
        const int c = m * 16 + hb * 4;
        uint32_t h0, l0, h1, l1;
        cvt2(res[0], q0, h0, l0);
        cvt2(res[1], q1, h1, l1);
        *(uint2*)((char*)g_pre_hi + ((size_t)row * 128 + c) * 2) = make_uint2(h0, h1);
        *(uint2*)((char*)g_pre_lo + ((size_t)row * 128 + c) * 2) = make_uint2(l0, l1);
    }
}

// =================================================================================
// Final GEMM (round-12 proven): out = pre @ Wm + bm.  32-row tiles, cp.async
// ingest of bf16 planes, 1024 blocks, 3 CTAs/SM, 3-term bf16.
// =================================================================================
__global__ void __launch_bounds__(256, 3) k_final(
    const float* __restrict__ bm, float* __restrict__ out)
{
    extern __shared__ char smem[];
    float* sBias = (float*)(smem + 2 * LO_F);
    const int tid = threadIdx.x;
    const uint32_t sb = smem_u32(smem);
    const int r0 = blockIdx.x * 32;

    #pragma unroll
    for (int it = 0; it < 4; it++) {
        const int idx = it * 256 + tid;      // 1024 16B chunks
        const int pl = idx >> 9;             // 0 hi, 1 lo
        const int r = (idx >> 4) & 31;
        const int seg = idx & 15;
        const __nv_bfloat16* src = (pl ? g_pre_lo : g_pre_hi)
                                   + (size_t)(r0 + r) * 128 + seg * 8;
        cp16(sb + pl * LO_F + r * 272 + seg * 16, src);
    }
    asm volatile("cp.async.commit_group;" ::: "memory");
    if (tid < 128) sBias[tid] = bm[tid];
    asm volatile("cp.async.wait_group 0;" ::: "memory");
    __syncthreads();

    const int l = tid & 31, w = tid >> 5;
    const int m0 = (w & 1) * 16;
    const int n0 = (w >> 1) * 32;
    const uint32_t aB = sb + (uint32_t)(m0 + (l & 15)) * 272 + ((l >> 4) << 4);
    const int fragBase = (n0 >> 3) * 1024 + l * 4;

    float acc[4][4];
    #pragma unroll
    for (int i = 0; i < 4; i++)
        #pragma unroll
        for (int c = 0; c < 4; c++) acc[i][c] = 0.f;
    mma_loop3<4, 1, LO_F>(aB, g_Wm_hi, g_Wm_lo, fragBase, acc);

    const int rl = l >> 2, nc = (l & 3) * 2;
    const int grow0 = r0 + m0 + rl;
    const int grow1 = grow0 + 8;
    #pragma unroll
    for (int j = 0; j < 4; j++) {
        const int n = n0 + j * 8 + nc;
        const float b0 = sBias[n], b1 = sBias[n + 1];
        *(float2*)(out + (size_t)grow0 * 128 + n)
            = make_float2(acc[j][0] + b0, acc[j][1] + b1);
        *(float2*)(out + (size_t)grow1 * 128 + n)
            = make_float2(acc[j][2] + b0, acc[j][3] + b1);
    }
}

// =================================================================================
extern "C" void kernel_launch(void* const* d_in, const int* in_sizes, int n_in,
                              void* d_out, int out_size)
{
    const float* z_q = (const float*)d_in[0];
    const float* x0  = (const float*)d_in[1];
    const float* x1  = (const float*)d_in[2];
    const float* p_q = (const float*)d_in[3];
    const float* Wq  = (const float*)d_in[4];
    const float* bq  = (const float*)d_in[5];
    const float* Wd  = (const float*)d_in[6];
    const float* bd  = (const float*)d_in[7];
    const float* Wa  = (const float*)d_in[8];
    const float* ba  = (const float*)d_in[9];
    const float* Wp  = (const float*)d_in[10];
    const float* bp  = (const float*)d_in[11];
    const float* Wm  = (const float*)d_in[12];
    const float* bm  = (const float*)d_in[13];
    float* out = (float*)d_out;

    const int MEGA_SMEM  = 2 * LO_A + 320 * 4;   // 36096
    const int FINAL_SMEM = 2 * LO_F + 128 * 4;   // 17920

    k_prep<<<72, 256>>>(Wq, Wd, Wa, Wp, Wm);
    // fused QDA (blocks 0..511, 2-term)  +  projections (blocks 512..1151, fp16)
    k_mega<<<1152, 256, MEGA_SMEM>>>(z_q, x0, x1, bq, bd, ba, bp);
    // sampling + attention dot -> bf16 hi/lo pre planes
    k_sample<<<8192, 256>>>(p_q);
    // out = pre @ Wm + bm  (32-row tiles, cp.async ingest, 3-term)
    k_final<<<1024, 256, FINAL_SMEM>>>(bm, out);
}

// round 17
// speedup vs baseline: 1.1612x; 1.0408x over previous
#include <cuda_runtime.h>
#include <cuda_bf16.h>
#include <cuda_fp16.h>
#include <math.h>
#include <stdint.h>

// ---------------- scratch (device globals; no allocation allowed) ----------------
__device__ float g_deltas[32768 * 128];          // [q][m*16 + l*8 + k*2 + comp]
__device__ float g_A[32768 * 64];                // [q][m*8 + s]  (softmaxed)
__device__ __half g_wx0h[16 * 64 * 64 * 16];     // [b*8+m][y*64+x][c]  fp16
__device__ __half g_wx1h[16 * 128 * 128 * 16];
__device__ __half g_pre16[32768 * 128];          // sampled pre, single fp16 plane

// weights in MMA-FRAGMENT order: frag[nblk][ks][lane][2] pairs
__device__ __nv_bfloat16 g_Wq_hi[16384];                     // bf16 hi only (2-term QDA)
__device__ __nv_bfloat16 g_Wda_hi[24576];                    // Wd (n<128) ++ Wa, hi only
__device__ __half        g_Wp_h16[16384];                    // fp16 single plane (proj)
__device__ __half        g_Wm_h[16384], g_Wm_l[16384];       // fp16 hi + residual (final)

constexpr int LO_A    = 64 * 272;   // lo-plane byte offset for 64-row tiles (mega)
constexpr int PLANE_F = 32 * 272;   // single A-plane bytes for 32-row tiles (final)

// ---------------- helpers ----------------
__device__ __forceinline__ uint32_t smem_u32(const void* p) {
    uint32_t a;
    asm("{ .reg .u64 t; cvta.to.shared.u64 t, %1; cvt.u32.u64 %0, t; }" : "=r"(a) : "l"(p));
    return a;
}
__device__ __forceinline__ void ldm_x4(uint32_t* r, uint32_t addr) {
    asm volatile("ldmatrix.sync.aligned.m8n8.x4.shared.b16 {%0,%1,%2,%3}, [%4];"
        : "=r"(r[0]), "=r"(r[1]), "=r"(r[2]), "=r"(r[3]) : "r"(addr));
}
__device__ __forceinline__ void mma_bf16(float* d, const uint32_t* a, const uint32_t* b) {
    asm volatile("mma.sync.aligned.m16n8k16.row.col.f32.bf16.bf16.f32 "
        "{%0,%1,%2,%3}, {%4,%5,%6,%7}, {%8,%9}, {%0,%1,%2,%3};"
        : "+f"(d[0]), "+f"(d[1]), "+f"(d[2]), "+f"(d[3])
        : "r"(a[0]), "r"(a[1]), "r"(a[2]), "r"(a[3]), "r"(b[0]), "r"(b[1]));
}
__device__ __forceinline__ void mma_f16(float* d, const uint32_t* a, const uint32_t* b) {
    asm volatile("mma.sync.aligned.m16n8k16.row.col.f32.f16.f16.f32 "
        "{%0,%1,%2,%3}, {%4,%5,%6,%7}, {%8,%9}, {%0,%1,%2,%3};"
        : "+f"(d[0]), "+f"(d[1]), "+f"(d[2]), "+f"(d[3])
        : "r"(a[0]), "r"(a[1]), "r"(a[2]), "r"(a[3]), "r"(b[0]), "r"(b[1]));
}
__device__ __forceinline__ void cp16(uint32_t dst, const void* src) {
    asm volatile("cp.async.cg.shared.global [%0], [%1], 16;" :: "r"(dst), "l"(src) : "memory");
}
__device__ __forceinline__ void cvt2(float f0, float f1, uint32_t& hi, uint32_t& lo) {
    __nv_bfloat162 h2 = __floats2bfloat162_rn(f0, f1);
    float2 hb = __bfloat1622float2(h2);
    __nv_bfloat162 l2 = __floats2bfloat162_rn(f0 - hb.x, f1 - hb.y);
    hi = *reinterpret_cast<uint32_t*>(&h2);
    lo = *reinterpret_cast<uint32_t*>(&l2);
}

// load 64x128 fp32 tile -> hi/lo bf16 planes in smem (272B padded rows)
__device__ __forceinline__ void load_tile_fp32(const float* __restrict__ X,
                                               char* smem, int tid) {
    float4 v[8];
    #pragma unroll
    for (int it = 0; it < 8; it++) {
        const int idx = it * 256 + tid;
        v[it] = *(const float4*)(X + (idx >> 5) * 128 + ((idx & 31) << 2));
    }
    #pragma unroll
    for (int it = 0; it < 8; it++) {
        const int idx = it * 256 + tid;
        const int r = idx >> 5, c4 = (idx & 31) << 2;
        uint32_t h0, l0, h1, l1;
        cvt2(v[it].x, v[it].y, h0, l0);
        cvt2(v[it].z, v[it].w, h1, l1);
        *(uint2*)(smem + r * 272 + c4 * 2) = make_uint2(h0, h1);
        *(uint2*)(smem + LO_A + r * 272 + c4 * 2) = make_uint2(l0, l1);
    }
}

// load 64x128 fp32 tile -> SINGLE fp16 plane in smem (272B padded rows)
__device__ __forceinline__ void load_tile_h16(const float* __restrict__ X,
                                              char* smem, int tid) {
    float4 v[8];
    #pragma unroll
    for (int it = 0; it < 8; it++) {
        const int idx = it * 256 + tid;
        v[it] = *(const float4*)(X + (idx >> 5) * 128 + ((idx & 31) << 2));
    }
    #pragma unroll
    for (int it = 0; it < 8; it++) {
        const int idx = it * 256 + tid;
        const int r = idx >> 5, c4 = (idx & 31) << 2;
        __half2 a = __floats2half2_rn(v[it].x, v[it].y);
        __half2 b = __floats2half2_rn(v[it].z, v[it].w);
        *(uint2*)(smem + r * 272 + c4 * 2)
            = make_uint2(*reinterpret_cast<uint32_t*>(&a), *reinterpret_cast<uint32_t*>(&b));
    }
}

// 2-term bf16 mainloop (QDA): A hi/lo planes, B hi fragments only.
template <int NT, int MI, int LOFF>
__device__ __forceinline__ void mma_loop2(uint32_t aB,
    const __nv_bfloat16* __restrict__ Bh, int fragBase, float (*acc)[4])
{
    #pragma unroll
    for (int ks = 0; ks < 8; ks++) {
        uint32_t ah[MI][4], al[MI][4];
        #pragma unroll
        for (int mi = 0; mi < MI; mi++) {
            ldm_x4(ah[mi], aB + mi * 16 * 272 + ks * 32);
            ldm_x4(al[mi], aB + LOFF + mi * 16 * 272 + ks * 32);
        }
        uint32_t bh[NT][2];
        #pragma unroll
        for (int j = 0; j < NT; j++) {
            const int o = fragBase + j * 1024 + ks * 128;
            const uint2 vh = *(const uint2*)(Bh + o);
            bh[j][0] = vh.x; bh[j][1] = vh.y;
        }
        #pragma unroll
        for (int mi = 0; mi < MI; mi++)
            #pragma unroll
            for (int j = 0; j < NT; j++) {
                mma_bf16(acc[mi * NT + j], ah[mi], bh[j]);
                mma_bf16(acc[mi * NT + j], al[mi], bh[j]);
            }
    }
}

// single-term fp16 mainloop (projections): A single fp16 plane, B fp16 fragments.
template <int NT, int MI>
__device__ __forceinline__ void mma_loop_h(uint32_t aB,
    const __half* __restrict__ Bh, int fragBase, float (*acc)[4])
{
    #pragma unroll
    for (int ks = 0; ks < 8; ks++) {
        uint32_t ah[MI][4];
        #pragma unroll
        for (int mi = 0; mi < MI; mi++)
            ldm_x4(ah[mi], aB + mi * 16 * 272 + ks * 32);
        uint32_t bh[NT][2];
        #pragma unroll
        for (int j = 0; j < NT; j++) {
            const int o = fragBase + j * 1024 + ks * 128;
            const uint2 vh = *(const uint2*)(Bh + o);
            bh[j][0] = vh.x; bh[j][1] = vh.y;
        }
        #pragma unroll
        for (int mi = 0; mi < MI; mi++)
            #pragma unroll
            for (int j = 0; j < NT; j++)
                mma_f16(acc[mi * NT + j], ah[mi], bh[j]);
    }
}

// =================================================================================
// Weight prep (fragment-coalesced): warp <-> fragment; lane l writes its own pairs.
// 576 fragments: [0,128) Wq(bf16 hi), [128,320) Wda(bf16 hi), [320,448) Wp(fp16),
// [448,576) Wm(fp16 hi + fp16 residual).
// =================================================================================
__global__ void __launch_bounds__(256) k_prep(
    const float* __restrict__ Wq, const float* __restrict__ Wd,
    const float* __restrict__ Wa, const float* __restrict__ Wp,
    const float* __restrict__ Wm)
{
    const int t = blockIdx.x * 256 + threadIdx.x;   // 72 blocks = 18432 = 576*32
    const int lane = t & 31;
    const int frag = t >> 5;

    int kind, fragL;
    if (frag < 128)      { kind = 0; fragL = frag; }
    else if (frag < 320) { kind = 1; fragL = frag - 128; }
    else if (frag < 448) { kind = 2; fragL = frag - 320; }
    else                 { kind = 3; fragL = frag - 448; }

    const int nblk = fragL >> 3, ks = fragL & 7;
    const int n = nblk * 8 + (lane >> 2);
    const int k0 = ks * 16 + (lane & 3) * 2;

    float wv[4];
    #pragma unroll
    for (int i = 0; i < 4; i++) {
        const int k = k0 + (i >> 1) * 8 + (i & 1);
        wv[i] = (kind == 0) ? Wq[k * 128 + n]
              : (kind == 1) ? ((n < 128) ? Wd[k * 128 + n] : Wa[k * 64 + (n - 128)])
              : (kind == 2) ? Wp[k * 128 + n]
                            : Wm[k * 128 + n];
    }
    const int e = fragL * 128 + lane * 4;
    if (kind == 2) {
        __half2 a = __floats2half2_rn(wv[0], wv[1]);
        __half2 b = __floats2half2_rn(wv[2], wv[3]);
        *(uint2*)(g_Wp_h16 + e)
            = make_uint2(*reinterpret_cast<uint32_t*>(&a), *reinterpret_cast<uint32_t*>(&b));
    } else if (kind == 3) {
        __half2 h0 = __floats2half2_rn(wv[0], wv[1]);
        __half2 h1 = __floats2half2_rn(wv[2], wv[3]);
        float2 f0 = __half22float2(h0), f1 = __half22float2(h1);
        __half2 l0 = __floats2half2_rn(wv[0] - f0.x, wv[1] - f0.y);
        __half2 l1 = __floats2half2_rn(wv[2] - f1.x, wv[3] - f1.y);
        *(uint2*)(g_Wm_h + e)
            = make_uint2(*reinterpret_cast<uint32_t*>(&h0), *reinterpret_cast<uint32_t*>(&h1));
        *(uint2*)(g_Wm_l + e)
            = make_uint2(*reinterpret_cast<uint32_t*>(&l0), *reinterpret_cast<uint32_t*>(&l1));
    } else {
        uint32_t h0, l0, h1, l1;
        cvt2(wv[0], wv[1], h0, l0);
        cvt2(wv[2], wv[3], h1, l1);
        __nv_bfloat16* dhi = (kind == 0) ? g_Wq_hi : g_Wda_hi;
        *(uint2*)(dhi + e) = make_uint2(h0, h1);
    }
}

// =================================================================================
// MEGA kernel: blocks [0,512) = fused QDA (2-term); [512,1152) = projections (fp16).
// =================================================================================
__global__ void __launch_bounds__(256, 2) k_mega(
    const float* __restrict__ z_q, const float* __restrict__ x0,
    const float* __restrict__ x1,
    const float* __restrict__ bq, const float* __restrict__ bd,
    const float* __restrict__ ba, const float* __restrict__ bp)
{
    extern __shared__ char smem[];
    float* sBias = (float*)(smem + 2 * LO_A);
    const int tid = threadIdx.x;
    const uint32_t sb = smem_u32(smem);
    const int l = tid & 31, w = tid >> 5;
    const int m0 = (w & 1) * 32;
    const int rl = l >> 2, nc = (l & 3) * 2;
    const uint32_t aB = sb + (uint32_t)(m0 + (l & 15)) * 272 + ((l >> 4) << 4);

    if (blockIdx.x < 512) {
        // ================= QDA path (2-term bf16) =================
        const int r0 = blockIdx.x * 64;
        load_tile_fp32(z_q + (size_t)r0 * 128, smem, tid);
        if (tid < 128) sBias[tid] = bq[tid];
        else sBias[tid] = bd[tid - 128];
        if (tid < 64) sBias[256 + tid] = ba[tid];
        __syncthreads();

        // ---- GEMM1: zq = z @ Wq  (N=128, NT=4) ----
        {
            const int n0 = (w >> 1) * 32;
            const int fragBase = (n0 >> 3) * 1024 + l * 4;
            float acc[8][4];
            #pragma unroll
            for (int i = 0; i < 8; i++)
                #pragma unroll
                for (int c = 0; c < 4; c++) acc[i][c] = 0.f;
            mma_loop2<4, 2, LO_A>(aB, g_Wq_hi, fragBase, acc);
            __syncthreads();

            // epilogue: zq + bq -> SAME smem planes as bf16 hi/lo
            #pragma unroll
            for (int mi = 0; mi < 2; mi++) {
                const int row0 = m0 + mi * 16 + rl;
                #pragma unroll
                for (int j = 0; j < 4; j++) {
                    const int n = n0 + j * 8 + nc;
                    const float b0 = sBias[n], b1 = sBias[n + 1];
                    uint32_t h, lo;
                    cvt2(acc[mi * 4 + j][0] + b0, acc[mi * 4 + j][1] + b1, h, lo);
                    *(uint32_t*)(smem + row0 * 272 + n * 2) = h;
                    *(uint32_t*)(smem + LO_A + row0 * 272 + n * 2) = lo;
                    cvt2(acc[mi * 4 + j][2] + b0, acc[mi * 4 + j][3] + b1, h, lo);
                    *(uint32_t*)(smem + (row0 + 8) * 272 + n * 2) = h;
                    *(uint32_t*)(smem + LO_A + (row0 + 8) * 272 + n * 2) = lo;
                }
            }
        }
        __syncthreads();

        // ---- GEMM2: [deltas | A] = zq @ Wda  (N=192, NT=6) ----
        {
            const int n0 = (w >> 1) * 48;
            const int fragBase = (n0 >> 3) * 1024 + l * 4;
            float acc[12][4];
            #pragma unroll
            for (int i = 0; i < 12; i++)
                #pragma unroll
                for (int c = 0; c < 4; c++) acc[i][c] = 0.f;
            mma_loop2<6, 2, LO_A>(aB, g_Wda_hi, fragBase, acc);

            #pragma unroll
            for (int mi = 0; mi < 2; mi++) {
                const int grow0 = r0 + m0 + mi * 16 + rl;
                const int grow1 = grow0 + 8;
                #pragma unroll
                for (int j = 0; j < 6; j++) {
                    const int n = n0 + j * 8 + nc;
                    const float b0 = sBias[128 + n], b1 = sBias[128 + n + 1];
                    const float v00 = acc[mi * 6 + j][0] + b0, v01 = acc[mi * 6 + j][1] + b1;
                    const float v10 = acc[mi * 6 + j][2] + b0, v11 = acc[mi * 6 + j][3] + b1;
                    if (n < 128) {
                        *(float2*)(g_deltas + (size_t)grow0 * 128 + n) = make_float2(v00, v01);
                        *(float2*)(g_deltas + (size_t)grow1 * 128 + n) = make_float2(v10, v11);
                    } else {
                        float mx = fmaxf(v00, v01);
                        mx = fmaxf(mx, __shfl_xor_sync(0xffffffffu, mx, 1));
                        mx = fmaxf(mx, __shfl_xor_sync(0xffffffffu, mx, 2));
                        float e0 = expf(v00 - mx), e1 = expf(v01 - mx);
                        float s = e0 + e1;
                        s += __shfl_xor_sync(0xffffffffu, s, 1);
                        s += __shfl_xor_sync(0xffffffffu, s, 2);
                        const float inv = 1.f / s;
                        *(float2*)(g_A + (size_t)grow0 * 64 + (n - 128))
                            = make_float2(e0 * inv, e1 * inv);

                        float mx2 = fmaxf(v10, v11);
                        mx2 = fmaxf(mx2, __shfl_xor_sync(0xffffffffu, mx2, 1));
                        mx2 = fmaxf(mx2, __shfl_xor_sync(0xffffffffu, mx2, 2));
                        float f0 = expf(v10 - mx2), f1 = expf(v11 - mx2);
                        float s2 = f0 + f1;
                        s2 += __shfl_xor_sync(0xffffffffu, s2, 1);
                        s2 += __shfl_xor_sync(0xffffffffu, s2, 2);
                        const float inv2 = 1.f / s2;
                        *(float2*)(g_A + (size_t)grow1 * 64 + (n - 128))
                            = make_float2(f0 * inv2, f1 * inv2);
                    }
                }
            }
        }
    } else {
        // ================= projection path (single fp16 MMA) =================
        const int bid = blockIdx.x - 512;
        const float* Xsrc;
        __half* o16;
        int hwshift, r0;
        if (bid < 128) { Xsrc = x0; o16 = g_wx0h; hwshift = 12; r0 = bid * 64; }
        else { Xsrc = x1; o16 = g_wx1h; hwshift = 14; r0 = (bid - 128) * 64; }

        load_tile_h16(Xsrc + (size_t)r0 * 128, smem, tid);
        if (tid < 128) sBias[tid] = bp[tid];
        __syncthreads();

        const int n0 = (w >> 1) * 32;
        const int fragBase = (n0 >> 3) * 1024 + l * 4;
        float acc[8][4];
        #pragma unroll
        for (int i = 0; i < 8; i++)
            #pragma unroll
            for (int c = 0; c < 4; c++) acc[i][c] = 0.f;
        mma_loop_h<4, 2>(aB, g_Wp_h16, fragBase, acc);

        const int msk = (1 << hwshift) - 1;
        #pragma unroll
        for (int mi = 0; mi < 2; mi++) {
            const int grow0 = r0 + m0 + mi * 16 + rl;
            const int grow1 = grow0 + 8;
            #pragma unroll
            for (int j = 0; j < 4; j++) {
                const int n = n0 + j * 8 + nc;
                const float b0 = sBias[n], b1 = sBias[n + 1];
                const int mh = n >> 4, c = n & 15;
                __half* o0 = o16 + ((((size_t)((grow0 >> hwshift) * 8 + mh)) << hwshift)
                                   + (grow0 & msk)) * 16 + c;
                __half* o1 = o16 + ((((size_t)((grow1 >> hwshift) * 8 + mh)) << hwshift)
                                   + (grow1 & msk)) * 16 + c;
                *(__half2*)o0 = __floats2half2_rn(acc[mi*4+j][0] + b0, acc[mi*4+j][1] + b1);
                *(__half2*)o1 = __floats2half2_rn(acc[mi*4+j][2] + b0, acc[mi*4+j][3] + b1);
            }
        }
    }
}

// =================================================================================
// Sampler: 2 lanes per location, fp16 images, both levels per thread; writes pre
// as a SINGLE fp16 plane.  8192 blocks of 256.
// =================================================================================
__global__ void __launch_bounds__(256) k_sample(const float* __restrict__ p_q)
{
    const int t    = blockIdx.x * 256 + threadIdx.x;
    const int lane = t & 1;
    const int loc  = t >> 1;
    const int hb = loc & 3;
    const int qp = (loc >> 2) & 16383;
    const int n  = loc >> 16;
    const int b = n >> 3, m = n & 7;
    const int ks = qp >> 12;
    const int ws = (qp >> 5) & 127;
    const int hs = ((qp & 31) << 2) + hb;

    const float4* ap = (const float4*)(g_A + (b * 16384 + qp) * 64 + m * 8);
    const float4 A0 = ap[0], A1 = ap[1];

    const float* dptr = g_deltas + (b * 16384 + hs * 128 + ws) * 128 + m * 16 + ks * 2;
    const float2 d0 = *(const float2*)dptr;
    const float2 d1 = *(const float2*)(dptr + 8);
    const float2 pq = *(const float2*)(p_q + ((m & 1) * 16384 + hs * 128 + ws) * 2);

    float res[2];
    #pragma unroll
    for (int l = 0; l < 2; l++) {
        const int wl = l ? 128 : 64;
        const float sc = l ? 127.f : 63.f;
        const float mult = (float)wl / sc;
        const __half* img = (l ? g_wx1h : g_wx0h) + n * (wl * wl * 16) + lane * 8;
        const float2 dxy = l ? d1 : d0;

        const float ix = fmaf(fmaf(pq.x, sc, dxy.x), mult, -0.5f);
        const float iy = fmaf(fmaf(pq.y, sc, dxy.y), mult, -0.5f);
        const float xf = floorf(ix), yf = floorf(iy);
        const float fx1 = ix - xf, fy1 = iy - yf;
        const float fx0 = 1.f - fx1, fy0 = 1.f - fy1;
        const int x0 = (int)xf, y0 = (int)yf;

        float a0 = 0.f, a1 = 0.f, a2 = 0.f, a3 = 0.f;
        float a4 = 0.f, a5 = 0.f, a6 = 0.f, a7 = 0.f;
        #pragma unroll
        for (int tap = 0; tap < 4; tap++) {
            const int xi = x0 + (tap & 1);
            const int yi = y0 + (tap >> 1);
            const float w = ((tap & 1) ? fx1 : fx0) * ((tap >> 1) ? fy1 : fy0);
            if (xi >= 0 && xi < wl && yi >= 0 && yi < wl) {
                const uint4 v = *(const uint4*)(img + ((yi * wl + xi) << 4));
                const __half2* hp = (const __half2*)&v;
                float2 f0 = __half22float2(hp[0]);
                float2 f1 = __half22float2(hp[1]);
                float2 f2 = __half22float2(hp[2]);
                float2 f3 = __half22float2(hp[3]);
                a0 = fmaf(w, f0.x, a0); a1 = fmaf(w, f0.y, a1);
                a2 = fmaf(w, f1.x, a2); a3 = fmaf(w, f1.y, a3);
                a4 = fmaf(w, f2.x, a4); a5 = fmaf(w, f2.y, a5);
                a6 = fmaf(w, f3.x, a6); a7 = fmaf(w, f3.y, a7);
            }
        }
        res[l] = A0.x * a0 + A0.y * a1 + A0.z * a2 + A0.w * a3
               + A1.x * a4 + A1.y * a5 + A1.z * a6 + A1.w * a7;
    }
    const float q0 = __shfl_xor_sync(0xffffffffu, res[0], 1);
    const float q1 = __shfl_xor_sync(0xffffffffu, res[1], 1);
    if (lane == 0) {
        const int row = b * 16384 + qp;
        const int c = m * 16 + hb * 4;
        __half2 h0 = __floats2half2_rn(res[0], q0);
        __half2 h1 = __floats2half2_rn(res[1], q1);
        *(uint2*)(g_pre16 + (size_t)row * 128 + c)
            = make_uint2(*reinterpret_cast<uint32_t*>(&h0), *reinterpret_cast<uint32_t*>(&h1));
    }
}

// =================================================================================
// Final GEMM: out = pre16 @ (Wm_h + Wm_l) + bm.  Single fp16 A plane via cp.async,
// 2-term fp16 MMA.  32-row tiles, 1024 blocks, 4 CTAs/SM, 9.2 KB smem.
// =================================================================================
__global__ void __launch_bounds__(256, 4) k_final(
    const float* __restrict__ bm, float* __restrict__ out)
{
    extern __shared__ char smem[];
    float* sBias = (float*)(smem + PLANE_F);
    const int tid = threadIdx.x;
    const uint32_t sb = smem_u32(smem);
    const int r0 = blockIdx.x * 32;

    #pragma unroll
    for (int it = 0; it < 2; it++) {
        const int idx = it * 256 + tid;      // 512 16B chunks (32 rows x 256B)
        const int r = idx >> 4;
        const int seg = idx & 15;
        cp16(sb + r * 272 + seg * 16, g_pre16 + (size_t)(r0 + r) * 128 + seg * 8);
    }
    asm volatile("cp.async.commit_group;" ::: "memory");
    if (tid < 128) sBias[tid] = bm[tid];
    asm volatile("cp.async.wait_group 0;" ::: "memory");
    __syncthreads();

    const int l = tid & 31, w = tid >> 5;
    const int m0 = (w & 1) * 16;
    const int n0 = (w >> 1) * 32;
    const uint32_t aB = sb + (uint32_t)(m0 + (l & 15)) * 272 + ((l >> 4) << 4);
    const int fragBase = (n0 >> 3) * 1024 + l * 4;

    float acc[4][4];
    #pragma unroll
    for (int i = 0; i < 4; i++)
        #pragma unroll
        for (int c = 0; c < 4; c++) acc[i][c] = 0.f;

    #pragma unroll
    for (int ks = 0; ks < 8; ks++) {
        uint32_t ah[4];
        ldm_x4(ah, aB + ks * 32);
        uint32_t bh[4][2], bl[4][2];
        #pragma unroll
        for (int j = 0; j < 4; j++) {
            const int o = fragBase + j * 1024 + ks * 128;
            const uint2 vh = *(const uint2*)(g_Wm_h + o);
            const uint2 vl = *(const uint2*)(g_Wm_l + o);
            bh[j][0] = vh.x; bh[j][1] = vh.y;
            bl[j][0] = vl.x; bl[j][1] = vl.y;
        }
        #pragma unroll
        for (int j = 0; j < 4; j++) {
            mma_f16(acc[j], ah, bh[j]);
            mma_f16(acc[j], ah, bl[j]);
        }
    }

    const int rl = l >> 2, nc = (l & 3) * 2;
    const int grow0 = r0 + m0 + rl;
    const int grow1 = grow0 + 8;
    #pragma unroll
    for (int j = 0; j < 4; j++) {
        const int n = n0 + j * 8 + nc;
        const float b0 = sBias[n], b1 = sBias[n + 1];
        *(float2*)(out + (size_t)grow0 * 128 + n)
            = make_float2(acc[j][0] + b0, acc[j][1] + b1);
        *(float2*)(out + (size_t)grow1 * 128 + n)
            = make_float2(acc[j][2] + b0, acc[j][3] + b1);
    }
}

// =================================================================================
extern "C" void kernel_launch(void* const* d_in, const int* in_sizes, int n_in,
                              void* d_out, int out_size)
{
    const float* z_q = (const float*)d_in[0];
    const float* x0  = (const float*)d_in[1];
    const float* x1  = (const float*)d_in[2];
    const float* p_q = (const float*)d_in[3];
    const float* Wq  = (const float*)d_in[4];
    const float* bq  = (const float*)d_in[5];
    const float* Wd  = (const float*)d_in[6];
    const float* bd  = (const float*)d_in[7];
    const float* Wa  = (const float*)d_in[8];
    const float* ba  = (const float*)d_in[9];
    const float* Wp  = (const float*)d_in[10];
    const float* bp  = (const float*)d_in[11];
    const float* Wm  = (const float*)d_in[12];
    const float* bm  = (const float*)d_in[13];
    float* out = (float*)d_out;

    const int MEGA_SMEM  = 2 * LO_A + 320 * 4;   // 36096
    const int FINAL_SMEM = PLANE_F + 128 * 4;    // 9216

    k_prep<<<72, 256>>>(Wq, Wd, Wa, Wp, Wm);
    // fused QDA (blocks 0..511, 2-term)  +  projections (blocks 512..1151, fp16)
    k_mega<<<1152, 256, MEGA_SMEM>>>(z_q, x0, x1, bq, bd, ba, bp);
    // sampling + attention dot -> single fp16 pre plane
    k_sample<<<8192, 256>>>(p_q);
    // out = pre16 @ (Wm_h + Wm_l) + bm  (2-term fp16)
    k_final<<<1024, 256, FINAL_SMEM>>>(bm, out);
}